// round 9
// baseline (speedup 1.0000x reference)
#include <cuda_runtime.h>
#include <math.h>

// Problem shape (fixed by setup_inputs): B=32, grid=48, N=2304, D=1152, K=3
#define BB    32
#define NN    2304
#define DD    1152
#define KP    3
#define CELLS 256        // (48/3)^2
#define MAXC  16         // capacity per cell list (actual = 9)
#define D4    (DD/4)     // 288 float4 per row
#define TPB   288        // threads per block; == D4
#define CPB   8          // cells per block
#define GRPS  (CELLS/CPB)// 32 cell-groups per batch

// ---------------------------------------------------------------------------
// Fused kernel: one block per (batch, group of 8 consecutive cells).
//   1) detect position dtype (int32 vs int64 words),
//   2) block-reduce max_x over this batch's positions (L2-resident),
//   3) scan positions once; matched tokens push index AND padding multiplier,
//   4) 8x gather body: cell uniform per iteration, coalesced float4,
//      streaming cache hints (__ldcs / __stcs) to keep pos/pad L2-resident,
//   5) mask written after the gather (off critical path).
// 32 regs / single wave (7 blocks/SM x 148 >= 1024 blocks) is load-bearing.
// ---------------------------------------------------------------------------
__global__ __launch_bounds__(TPB)
void pool_fused(const int*           __restrict__ posw,
                const float*         __restrict__ hs,
                const unsigned char* __restrict__ pad,
                float*               __restrict__ out,
                float*               __restrict__ mask_f,          // may be null
                unsigned char*       __restrict__ mask_b,          // may be null
                int mask_f_elems, int mask_b_elems,
                float scale)
{
    const int blk  = blockIdx.x;          // b*GRPS + g
    const int b    = blk >> 5;            // GRPS == 32
    const int c0   = (blk & 31) * CPB;    // first cell of this block
    const int t    = threadIdx.x;         // 0..287
    const int warp = t >> 5;              // 0..8
    const int lane = t & 31;

    __shared__ int   idxs[CPB][MAXC];
    __shared__ float pmul[CPB][MAXC];
    __shared__ int   cnt_sh[CPB];
    __shared__ int   wmax[9];
    __shared__ int   mx_sh;

    if (t < CPB) cnt_sh[t] = 0;
    if (t < CPB * MAXC) idxs[t >> 4][t & 15] = 0;   // default -> token 0 (guarded)

    // --- dtype detection (parallel; barrier also covers the inits above) ---
    // int64 non-negative: every odd 32-bit word is 0.
    // int32 layout: odd words are y-coords, nonzero from token 48 onward.
    const int is32 = __syncthreads_or((t < 128) && (posw[2 * t + 1] != 0));
    const long long* __restrict__ posl = (const long long*)posw;

    // --- pass 1: block max of max(pos_x, 0) ---
    int m = 0;
    for (int n = t; n < NN; n += TPB) {
        int x;
        if (is32) {
            x = posw[((size_t)b * NN + n) * 2];
        } else {
            long long xl = posl[((size_t)b * NN + n) * 2];
            x = (xl > 0) ? (int)xl : 0;
        }
        if (x < 0) x = 0;
        m = max(m, x);
    }
    #pragma unroll
    for (int s = 16; s > 0; s >>= 1)
        m = max(m, __shfl_xor_sync(0xffffffffu, m, s));
    if (lane == 0) wmax[warp] = m;
    __syncthreads();
    if (t == 0) {
        int mm = wmax[0];
        #pragma unroll
        for (int w = 1; w < 9; w++) mm = max(mm, wmax[w]);
        mx_sh = mm;
    }
    __syncthreads();
    const int stride = (mx_sh + 1) / KP;    // max_x // K

    // --- pass 2: one scan serving all 8 cells (positions L1/L2-hot).
    //     Matched tokens push index + padding multiplier together. ---
    for (int n = t; n < NN; n += TPB) {
        int x, y;
        if (is32) {
            int2 p = ((const int2*)posw)[(size_t)b * NN + n];
            x = p.x; y = p.y;
        } else {
            longlong2 p = ((const longlong2*)posl)[(size_t)b * NN + n];
            x = (p.x > 0) ? (int)p.x : 0;
            y = (p.y > 0) ? (int)p.y : 0;
        }
        if (x < 0) x = 0;
        if (y < 0) y = 0;
        const int seg = (x / KP) + stride * (y / KP);
        const int rel = seg - c0;
        if ((unsigned)rel < CPB) {
            const int slot = atomicAdd(&cnt_sh[rel], 1);
            if (slot < MAXC) {
                idxs[rel][slot] = n;
                pmul[rel][slot] = pad[(size_t)b * NN + n] ? 0.0f : 1.0f;
            }
        }
    }
    __syncthreads();

    // --- main gather: 8x body; cell uniform across block per iteration.
    //     __ldcs/__stcs: evict-first streaming, keeps pos/pad in L2. ---
    const float4* __restrict__ base =
        (const float4*)hs + (size_t)b * NN * D4;
    float4* __restrict__ obase =
        (float4*)out + ((size_t)(b * CELLS + c0)) * D4 + t;

    #pragma unroll
    for (int c = 0; c < CPB; c++) {
        const int cnt = min(cnt_sh[c], MAXC);
        float ax = 0.f, ay = 0.f, az = 0.f, aw = 0.f;
        #pragma unroll 4
        for (int i = 0; i < cnt; i++) {
            const int   n = idxs[c][i];
            const float p = pmul[c][i];
            float4 v = __ldcs(base + (size_t)n * D4 + t);
            ax = fmaf(v.x, p, ax);
            ay = fmaf(v.y, p, ay);
            az = fmaf(v.z, p, az);
            aw = fmaf(v.w, p, aw);
        }
        float4 o;
        o.x = ax * scale; o.y = ay * scale; o.z = az * scale; o.w = aw * scale;
        __stcs(obase + (size_t)c * D4, o);
    }

    // --- validity mask (off critical path; cnt_sh still live) ---
    if (t < CPB) {
        const int midx  = b * CELLS + c0 + t;
        const int valid = (cnt_sh[t] > 0) ? 1 : 0;
        if (mask_f && midx < mask_f_elems) mask_f[midx] = (float)valid;
        if (mask_b && midx < mask_b_elems) mask_b[midx] = (unsigned char)valid;
    }
}

// ---------------------------------------------------------------------------
extern "C" void kernel_launch(void* const* d_in, const int* in_sizes, int n_in,
                              void* d_out, int out_size)
{
    const float*         hs   = (const float*)d_in[0];
    const int*           posw = (const int*)d_in[1];
    const unsigned char* pad  = (const unsigned char*)d_in[2];
    float* out = (float*)d_out;

    const int pooled_elems = BB * CELLS * DD;     // 9,437,184
    int extra = out_size - pooled_elems;          // tail beyond pooled, in floats

    float* mask_f = 0; unsigned char* mask_b = 0;
    int mf = 0, mb = 0;
    if (extra >= BB * CELLS) {                    // mask stored as float32
        mask_f = out + pooled_elems;
        mf = BB * CELLS;
    } else if (extra * 4 >= BB * CELLS) {         // mask stored as bool bytes
        mask_b = (unsigned char*)(out + pooled_elems);
        mb = BB * CELLS;
    }

    const float scale = sqrtf((float)DD) / (float)(KP * KP);

    pool_fused<<<BB * GRPS, TPB>>>(posw, hs, pad, out,
                                   mask_f, mask_b, mf, mb, scale);
}